// round 1
// baseline (speedup 1.0000x reference)
#include <cuda_runtime.h>
#include <math.h>

// Problem constants
#define BB   16
#define CC   256
#define NN   4096                      // H*W
#define SPAD 68                        // padded shared stride (reduces store conflicts, keeps float4 alignment: 68*4=272B % 16 == 0)

// Scratch (device globals — allocation-free per harness rules)
static __device__ float g_inv1[BB * CC];
static __device__ float g_inv2[BB * CC];
static __device__ float g_attn1[BB * CC * CC];   // 4 MB, scores -> softmaxed in place
static __device__ float g_attn2[BB * CC * CC];

// ---------------------------------------------------------------------------
// Kernel 1: per-row (b,c) inverse L2 norms of x1 and x2 over N=4096
// ---------------------------------------------------------------------------
__global__ void __launch_bounds__(256) norm_k(const float* __restrict__ x1,
                                              const float* __restrict__ x2) {
    const int row = blockIdx.x;                       // b*CC + c
    const float4* p1 = (const float4*)(x1 + (size_t)row * NN);
    const float4* p2 = (const float4*)(x2 + (size_t)row * NN);
    float s1 = 0.f, s2 = 0.f;
    for (int i = threadIdx.x; i < NN / 4; i += blockDim.x) {
        float4 a = p1[i], b = p2[i];
        s1 += a.x * a.x + a.y * a.y + a.z * a.z + a.w * a.w;
        s2 += b.x * b.x + b.y * b.y + b.z * b.z + b.w * b.w;
    }
    __shared__ float sh1[8], sh2[8];
    const int lane = threadIdx.x & 31, w = threadIdx.x >> 5;
    #pragma unroll
    for (int o = 16; o; o >>= 1) {
        s1 += __shfl_xor_sync(0xffffffffu, s1, o);
        s2 += __shfl_xor_sync(0xffffffffu, s2, o);
    }
    if (lane == 0) { sh1[w] = s1; sh2[w] = s2; }
    __syncthreads();
    if (threadIdx.x < 32) {
        s1 = (lane < 8) ? sh1[lane] : 0.f;
        s2 = (lane < 8) ? sh2[lane] : 0.f;
        #pragma unroll
        for (int o = 4; o; o >>= 1) {
            s1 += __shfl_xor_sync(0xffffffffu, s1, o);
            s2 += __shfl_xor_sync(0xffffffffu, s2, o);
        }
        if (lane == 0) {
            g_inv1[row] = 1.f / fmaxf(sqrtf(s1), 1e-12f);
            g_inv2[row] = 1.f / fmaxf(sqrtf(s2), 1e-12f);
        }
    }
}

// ---------------------------------------------------------------------------
// Kernel 2: score GEMMs.  S1 = s @ x11^T, S2 = s @ x21^T, s = x11 + x21.
// Tiles 64x64, BK=16, 256 threads, 4x4 microtile, dual accumulators (A reuse).
// Normalization applied on the fly via g_inv*.
// ---------------------------------------------------------------------------
__global__ void __launch_bounds__(256) score_k(const float* __restrict__ x1,
                                               const float* __restrict__ x2) {
    const int b  = blockIdx.z;
    const int c0 = blockIdx.y * 64;        // output rows  (softmax dim is cols)
    const int d0 = blockIdx.x * 64;        // output cols
    const int tid = threadIdx.x;

    const int lrow = tid >> 2;             // 0..63, tile row this thread loads
    const int lk   = (tid & 3) * 4;        // 0,4,8,12 : k offset (float4)
    const int ty   = tid >> 4;             // 0..15
    const int tx   = tid & 15;             // 0..15

    __shared__ float Ss [16][SPAD];        // s  tile, [k][row]
    __shared__ float B1s[16][SPAD];        // x11 tile
    __shared__ float B2s[16][SPAD];        // x21 tile

    const float* xa1 = x1 + ((size_t)(b * CC + c0 + lrow)) * NN + lk;
    const float* xa2 = x2 + ((size_t)(b * CC + c0 + lrow)) * NN + lk;
    const float* xb1 = x1 + ((size_t)(b * CC + d0 + lrow)) * NN + lk;
    const float* xb2 = x2 + ((size_t)(b * CC + d0 + lrow)) * NN + lk;
    const float iA1 = g_inv1[b * CC + c0 + lrow];
    const float iA2 = g_inv2[b * CC + c0 + lrow];
    const float iB1 = g_inv1[b * CC + d0 + lrow];
    const float iB2 = g_inv2[b * CC + d0 + lrow];

    float acc1[4][4] = {{0.f}}, acc2[4][4] = {{0.f}};

    for (int kk = 0; kk < NN; kk += 16) {
        float4 a1 = *(const float4*)(xa1 + kk);
        float4 a2 = *(const float4*)(xa2 + kk);
        float4 b1 = *(const float4*)(xb1 + kk);
        float4 b2 = *(const float4*)(xb2 + kk);
        __syncthreads();   // previous iteration's reads done before overwrite
        Ss [lk + 0][lrow] = a1.x * iA1 + a2.x * iA2;
        Ss [lk + 1][lrow] = a1.y * iA1 + a2.y * iA2;
        Ss [lk + 2][lrow] = a1.z * iA1 + a2.z * iA2;
        Ss [lk + 3][lrow] = a1.w * iA1 + a2.w * iA2;
        B1s[lk + 0][lrow] = b1.x * iB1;
        B1s[lk + 1][lrow] = b1.y * iB1;
        B1s[lk + 2][lrow] = b1.z * iB1;
        B1s[lk + 3][lrow] = b1.w * iB1;
        B2s[lk + 0][lrow] = b2.x * iB2;
        B2s[lk + 1][lrow] = b2.y * iB2;
        B2s[lk + 2][lrow] = b2.z * iB2;
        B2s[lk + 3][lrow] = b2.w * iB2;
        __syncthreads();
        #pragma unroll
        for (int k = 0; k < 16; ++k) {
            float4 av  = *(const float4*)&Ss [k][ty * 4];
            float4 bv1 = *(const float4*)&B1s[k][tx * 4];
            float4 bv2 = *(const float4*)&B2s[k][tx * 4];
            float a[4]  = {av.x,  av.y,  av.z,  av.w};
            float p1[4] = {bv1.x, bv1.y, bv1.z, bv1.w};
            float p2[4] = {bv2.x, bv2.y, bv2.z, bv2.w};
            #pragma unroll
            for (int i = 0; i < 4; ++i)
                #pragma unroll
                for (int j = 0; j < 4; ++j) {
                    acc1[i][j] = fmaf(a[i], p1[j], acc1[i][j]);
                    acc2[i][j] = fmaf(a[i], p2[j], acc2[i][j]);
                }
        }
    }

    const size_t obase = (size_t)b * CC * CC;
    #pragma unroll
    for (int i = 0; i < 4; ++i) {
        const int c = c0 + ty * 4 + i;
        float4 o1 = make_float4(acc1[i][0], acc1[i][1], acc1[i][2], acc1[i][3]);
        float4 o2 = make_float4(acc2[i][0], acc2[i][1], acc2[i][2], acc2[i][3]);
        *(float4*)(g_attn1 + obase + (size_t)c * CC + d0 + tx * 4) = o1;
        *(float4*)(g_attn2 + obase + (size_t)c * CC + d0 + tx * 4) = o2;
    }
}

// ---------------------------------------------------------------------------
// Kernel 3: row softmax over last axis (256), in place. 8192 rows.
// ---------------------------------------------------------------------------
__global__ void __launch_bounds__(256) softmax_k() {
    const int idx = blockIdx.x;                             // 0 .. 2*BB*CC-1
    float* p = ((idx < BB * CC) ? g_attn1 : g_attn2) +
               (size_t)(idx & (BB * CC - 1)) * CC;
    const int lane = threadIdx.x & 31, w = threadIdx.x >> 5;
    __shared__ float sh[8];
    __shared__ float s_bcast;

    float v = p[threadIdx.x];

    // max
    float m = v;
    #pragma unroll
    for (int o = 16; o; o >>= 1) m = fmaxf(m, __shfl_xor_sync(0xffffffffu, m, o));
    if (lane == 0) sh[w] = m;
    __syncthreads();
    if (threadIdx.x < 32) {
        float t = (lane < 8) ? sh[lane] : -INFINITY;
        #pragma unroll
        for (int o = 4; o; o >>= 1) t = fmaxf(t, __shfl_xor_sync(0xffffffffu, t, o));
        if (lane == 0) s_bcast = t;
    }
    __syncthreads();
    m = s_bcast;

    float e = expf(v - m);

    // sum
    float s = e;
    #pragma unroll
    for (int o = 16; o; o >>= 1) s += __shfl_xor_sync(0xffffffffu, s, o);
    __syncthreads();          // sh reuse guard
    if (lane == 0) sh[w] = s;
    __syncthreads();
    if (threadIdx.x < 32) {
        float t = (lane < 8) ? sh[lane] : 0.f;
        #pragma unroll
        for (int o = 4; o; o >>= 1) t += __shfl_xor_sync(0xffffffffu, t, o);
        if (lane == 0) s_bcast = t;
    }
    __syncthreads();

    p[threadIdx.x] = e * (1.f / s_bcast);
}

// ---------------------------------------------------------------------------
// Kernel 4: projection GEMMs + transpose + residual, fused.
//   out[b, n*256+c] = sum_d attn1[b,c,d]*x1[b,d,n] + sum_d attn2[b,c,d]*x2[b,d,n]
//                   + x1[b, n*256+c] + x2[b, n*256+c]
// Tiles: 64 (n) x 64 (c), K = 256 (d), BK = 16, 256 threads, 4x4 microtile.
// ---------------------------------------------------------------------------
__global__ void __launch_bounds__(256) proj_k(const float* __restrict__ x1,
                                              const float* __restrict__ x2,
                                              float* __restrict__ out) {
    const int b  = blockIdx.z;
    const int n0 = blockIdx.y * 64;
    const int c0 = blockIdx.x * 64;
    const int tid = threadIdx.x;

    const int dk   = tid >> 4;            // 0..15: d offset for X tile load
    const int j4   = (tid & 15) * 4;      // n offset within tile (float4)
    const int lrow = tid >> 2;            // 0..63: c row for attn tile load
    const int lk   = (tid & 3) * 4;       // d offset (float4)
    const int ty   = tid >> 4;            // n sub-tile
    const int tx   = tid & 15;            // c sub-tile

    __shared__ float X1s[16][SPAD];       // [d][n]
    __shared__ float X2s[16][SPAD];
    __shared__ float A1s[16][SPAD];       // [d][c]
    __shared__ float A2s[16][SPAD];

    float z1[4][4] = {{0.f}}, z2[4][4] = {{0.f}};
    const size_t abase = (size_t)b * CC * CC;

    for (int kk = 0; kk < CC; kk += 16) {
        float4 xv1 = *(const float4*)(x1 + ((size_t)(b * CC + kk + dk)) * NN + n0 + j4);
        float4 xv2 = *(const float4*)(x2 + ((size_t)(b * CC + kk + dk)) * NN + n0 + j4);
        float4 a1  = *(const float4*)(g_attn1 + abase + (size_t)(c0 + lrow) * CC + kk + lk);
        float4 a2  = *(const float4*)(g_attn2 + abase + (size_t)(c0 + lrow) * CC + kk + lk);
        __syncthreads();
        *(float4*)&X1s[dk][j4] = xv1;
        *(float4*)&X2s[dk][j4] = xv2;
        A1s[lk + 0][lrow] = a1.x;
        A1s[lk + 1][lrow] = a1.y;
        A1s[lk + 2][lrow] = a1.z;
        A1s[lk + 3][lrow] = a1.w;
        A2s[lk + 0][lrow] = a2.x;
        A2s[lk + 1][lrow] = a2.y;
        A2s[lk + 2][lrow] = a2.z;
        A2s[lk + 3][lrow] = a2.w;
        __syncthreads();
        #pragma unroll
        for (int k = 0; k < 16; ++k) {
            float4 xa = *(const float4*)&X1s[k][ty * 4];
            float4 xb = *(const float4*)&X2s[k][ty * 4];
            float4 w1 = *(const float4*)&A1s[k][tx * 4];
            float4 w2 = *(const float4*)&A2s[k][tx * 4];
            float u[4] = {xa.x, xa.y, xa.z, xa.w};
            float v[4] = {xb.x, xb.y, xb.z, xb.w};
            float p[4] = {w1.x, w1.y, w1.z, w1.w};
            float q[4] = {w2.x, w2.y, w2.z, w2.w};
            #pragma unroll
            for (int i = 0; i < 4; ++i)
                #pragma unroll
                for (int j = 0; j < 4; ++j) {
                    z1[i][j] = fmaf(u[i], p[j], z1[i][j]);
                    z2[i][j] = fmaf(v[i], q[j], z2[i][j]);
                }
        }
    }

    // Fused transpose + residual epilogue. Flat out index o = n*CC + c.
    const size_t ob = (size_t)b * CC * NN;
    #pragma unroll
    for (int i = 0; i < 4; ++i) {
        const int n = n0 + ty * 4 + i;
        const size_t o = ob + (size_t)n * CC + c0 + tx * 4;
        float4 r1 = *(const float4*)(x1 + o);
        float4 r2 = *(const float4*)(x2 + o);
        float4 w;
        w.x = z1[i][0] + z2[i][0] + r1.x + r2.x;
        w.y = z1[i][1] + z2[i][1] + r1.y + r2.y;
        w.z = z1[i][2] + z2[i][2] + r1.z + r2.z;
        w.w = z1[i][3] + z2[i][3] + r1.w + r2.w;
        *(float4*)(out + o) = w;
    }
}

// ---------------------------------------------------------------------------
extern "C" void kernel_launch(void* const* d_in, const int* in_sizes, int n_in,
                              void* d_out, int out_size) {
    const float* x1 = (const float*)d_in[0];
    const float* x2 = (const float*)d_in[1];
    float* out = (float*)d_out;

    norm_k   <<<BB * CC, 256>>>(x1, x2);
    score_k  <<<dim3(4, 4, BB), 256>>>(x1, x2);
    softmax_k<<<2 * BB * CC, 256>>>();
    proj_k   <<<dim3(4, 64, BB), 256>>>(x1, x2, out);
}

// round 3
// speedup vs baseline: 4.6698x; 4.6698x over previous
#include <cuda_runtime.h>
#include <cuda_bf16.h>
#include <cstdint>
#include <math.h>

#define BB 16
#define CC 256
#define NN 4096

// ---------------------------------------------------------------------------
// Device-global scratch (allocation-free per harness rules)
// ---------------------------------------------------------------------------
static __device__ __nv_bfloat16 g_s  [(size_t)BB * CC * NN];  // s = x11 + x21
static __device__ __nv_bfloat16 g_x11[(size_t)BB * CC * NN];  // x1 row-normalized
static __device__ __nv_bfloat16 g_x21[(size_t)BB * CC * NN];  // x2 row-normalized
static __device__ __nv_bfloat16 g_x1t[(size_t)BB * CC * NN];  // x1 transposed [b,n,d]
static __device__ __nv_bfloat16 g_x2t[(size_t)BB * CC * NN];
static __device__ float g_attn1[(size_t)BB * CC * CC];        // raw scores fp32
static __device__ float g_attn2[(size_t)BB * CC * CC];
static __device__ __nv_bfloat16 g_ab1[(size_t)BB * CC * CC];  // softmaxed, bf16
static __device__ __nv_bfloat16 g_ab2[(size_t)BB * CC * CC];

// ---------------------------------------------------------------------------
// PTX helpers (base PTX only: cp.async / ldmatrix / mma.sync — compute_103 safe)
// ---------------------------------------------------------------------------
__device__ __forceinline__ uint32_t smem_to_u32(const void* p) {
    uint32_t a;
    asm("{ .reg .u64 t; cvta.to.shared.u64 t, %1; cvt.u32.u64 %0, t; }"
        : "=r"(a) : "l"(p));
    return a;
}

__device__ __forceinline__ void cp16(uint32_t dst, const void* src) {
    asm volatile("cp.async.cg.shared.global [%0], [%1], 16;\n"
                 :: "r"(dst), "l"(src));
}
__device__ __forceinline__ void cp_commit() {
    asm volatile("cp.async.commit_group;" ::: "memory");
}
template <int N>
__device__ __forceinline__ void cp_wait() {
    asm volatile("cp.async.wait_group %0;" :: "n"(N) : "memory");
}

__device__ __forceinline__ void ldsm4(uint32_t* r, uint32_t addr) {
    asm volatile("ldmatrix.sync.aligned.m8n8.x4.shared.b16 {%0,%1,%2,%3}, [%4];"
                 : "=r"(r[0]), "=r"(r[1]), "=r"(r[2]), "=r"(r[3])
                 : "r"(addr));
}

__device__ __forceinline__ void mma16816(float* c, const uint32_t* a,
                                         uint32_t b0, uint32_t b1) {
    asm volatile(
        "mma.sync.aligned.m16n8k16.row.col.f32.bf16.bf16.f32 "
        "{%0,%1,%2,%3}, {%4,%5,%6,%7}, {%8,%9}, {%0,%1,%2,%3};"
        : "+f"(c[0]), "+f"(c[1]), "+f"(c[2]), "+f"(c[3])
        : "r"(a[0]), "r"(a[1]), "r"(a[2]), "r"(a[3]), "r"(b0), "r"(b1));
}

__device__ __forceinline__ uint32_t pack2bf(float x, float y) {
    __nv_bfloat162 h = __floats2bfloat162_rn(x, y);
    return *reinterpret_cast<uint32_t*>(&h);
}
__device__ __forceinline__ uint2 pack4bf(float a, float b, float c, float d) {
    return make_uint2(pack2bf(a, b), pack2bf(c, d));
}

// Tile buffers: per buffer A(128x64 bf16 = 16KB) + B(16KB); two buffers = 64KB.
#define BUF_STRIDE 32768
#define GEMM_SMEM  (2 * BUF_STRIDE)

// ---------------------------------------------------------------------------
// Kernel 1: fused norm + bf16 conversion.  One block per (b,c) row.
// ---------------------------------------------------------------------------
__global__ void __launch_bounds__(256) fuse_k(const float* __restrict__ x1,
                                              const float* __restrict__ x2) {
    const int row = blockIdx.x;
    const size_t base4 = (size_t)row * (NN / 4);
    const float4* p1 = ((const float4*)x1) + base4;
    const float4* p2 = ((const float4*)x2) + base4;

    float4 a[4], c[4];
    float s1 = 0.f, s2 = 0.f;
    #pragma unroll
    for (int i = 0; i < 4; ++i) {
        a[i] = p1[threadIdx.x + i * 256];
        c[i] = p2[threadIdx.x + i * 256];
        s1 += a[i].x * a[i].x + a[i].y * a[i].y + a[i].z * a[i].z + a[i].w * a[i].w;
        s2 += c[i].x * c[i].x + c[i].y * c[i].y + c[i].z * c[i].z + c[i].w * c[i].w;
    }
    __shared__ float sh1[8], sh2[8];
    __shared__ float b_i1, b_i2;
    const int lane = threadIdx.x & 31, w = threadIdx.x >> 5;
    #pragma unroll
    for (int o = 16; o; o >>= 1) {
        s1 += __shfl_xor_sync(0xffffffffu, s1, o);
        s2 += __shfl_xor_sync(0xffffffffu, s2, o);
    }
    if (lane == 0) { sh1[w] = s1; sh2[w] = s2; }
    __syncthreads();
    if (threadIdx.x < 32) {
        s1 = (lane < 8) ? sh1[lane] : 0.f;
        s2 = (lane < 8) ? sh2[lane] : 0.f;
        #pragma unroll
        for (int o = 4; o; o >>= 1) {
            s1 += __shfl_xor_sync(0xffffffffu, s1, o);
            s2 += __shfl_xor_sync(0xffffffffu, s2, o);
        }
        if (lane == 0) {
            b_i1 = 1.f / fmaxf(sqrtf(s1), 1e-12f);
            b_i2 = 1.f / fmaxf(sqrtf(s2), 1e-12f);
        }
    }
    __syncthreads();
    const float i1 = b_i1, i2 = b_i2;

    uint2* os  = reinterpret_cast<uint2*>(g_s)   + base4;
    uint2* o11 = reinterpret_cast<uint2*>(g_x11) + base4;
    uint2* o21 = reinterpret_cast<uint2*>(g_x21) + base4;
    #pragma unroll
    for (int i = 0; i < 4; ++i) {
        const int idx = threadIdx.x + i * 256;
        float n1x = a[i].x * i1, n1y = a[i].y * i1, n1z = a[i].z * i1, n1w = a[i].w * i1;
        float n2x = c[i].x * i2, n2y = c[i].y * i2, n2z = c[i].z * i2, n2w = c[i].w * i2;
        o11[idx] = pack4bf(n1x, n1y, n1z, n1w);
        o21[idx] = pack4bf(n2x, n2y, n2z, n2w);
        os [idx] = pack4bf(n1x + n2x, n1y + n2y, n1z + n2z, n1w + n2w);
    }
}

// ---------------------------------------------------------------------------
// Kernel 2: transpose x1, x2 -> bf16 [b, n, d]
// ---------------------------------------------------------------------------
__global__ void __launch_bounds__(256) transpose_k(const float* __restrict__ x1,
                                                   const float* __restrict__ x2) {
    __shared__ float t1[32][33], t2[32][33];
    const int b  = blockIdx.z;
    const int c0 = blockIdx.y * 32;
    const int n0 = blockIdx.x * 32;
    const int tx = threadIdx.x, ty = threadIdx.y;   // 32 x 8

    #pragma unroll
    for (int i = 0; i < 4; ++i) {
        const int r = ty + i * 8;
        const size_t idx = ((size_t)(b * CC + c0 + r)) * NN + n0 + tx;
        t1[r][tx] = x1[idx];
        t2[r][tx] = x2[idx];
    }
    __syncthreads();
    #pragma unroll
    for (int i = 0; i < 4; ++i) {
        const int r = ty + i * 8;
        const size_t o = ((size_t)b * NN + n0 + r) * CC + c0 + tx;
        g_x1t[o] = __float2bfloat16_rn(t1[tx][r]);
        g_x2t[o] = __float2bfloat16_rn(t2[tx][r]);
    }
}

// ---------------------------------------------------------------------------
// Kernel 3: score GEMM, mma.sync bf16.
//   Per batch: D[256, 512] = s[256, 4096] @ [x11 ; x21]^T
//   CTA tile 128x128, BK=64, 8 warps (2x4), warp tile 64x32, double-buffered
//   cp.async pipeline, XOR-swizzled smem (conflict-free ldmatrix).
//   nIdx 0,1 -> attn1 (d0 = 0,128); nIdx 2,3 -> attn2.
// ---------------------------------------------------------------------------
__global__ void __launch_bounds__(256) score_mma() {
    extern __shared__ char smem[];
    const uint32_t sb = smem_to_u32(smem);
    const int tid = threadIdx.x, lane = tid & 31, wid = tid >> 5;
    const int b    = blockIdx.z;
    const int m0   = blockIdx.y * 128;
    const int nIdx = blockIdx.x;                  // 0..3
    const int d0   = (nIdx & 1) * 128;

    float* gOut = (nIdx < 2 ? g_attn1 : g_attn2) + (size_t)b * CC * CC;
    const __nv_bfloat16* bsrc = (nIdx < 2) ? g_x11 : g_x21;
    const uint4* gA = (const uint4*)g_s  + (size_t)(b * CC + m0) * (NN / 8);
    const uint4* gB = (const uint4*)bsrc + (size_t)(b * CC + d0) * (NN / 8);

    const int mW = (wid >> 2) * 64;               // warp m offset
    const int nW = (wid & 3) * 32;                // warp n offset
    const int lrow = lane & 15;
    const int lhi  = lane >> 4;

    float acc[4][4][4] = {};

    // prefetch chunk ch into buffer buf
    auto prefetch = [&](int ch, int buf) {
        const uint32_t aB = sb + buf * BUF_STRIDE;
        const uint32_t bB = aB + 16384;
        #pragma unroll
        for (int i = 0; i < 4; ++i) {
            const int lin = i * 256 + tid;
            const int r = lin >> 3, c = lin & 7;
            const uint32_t off = r * 128 + ((c ^ (r & 7)) << 4);
            cp16(aB + off, gA + (size_t)r * (NN / 8) + ch * 8 + c);
            cp16(bB + off, gB + (size_t)r * (NN / 8) + ch * 8 + c);
        }
        cp_commit();
    };

    prefetch(0, 0);
    for (int ch = 0; ch < NN / 64; ++ch) {
        const int buf = ch & 1;
        if (ch + 1 < NN / 64) { prefetch(ch + 1, buf ^ 1); cp_wait<1>(); }
        else                  { cp_wait<0>(); }
        __syncthreads();

        const uint32_t aB = sb + buf * BUF_STRIDE;
        const uint32_t bB = aB + 16384;
        #pragma unroll
        for (int ks = 0; ks < 4; ++ks) {
            uint32_t afr[4][4], bfr[2][4];
            #pragma unroll
            for (int mi = 0; mi < 4; ++mi) {
                const int r = mW + 16 * mi + lrow;
                ldsm4(afr[mi], aB + r * 128 + ((((ks << 1) | lhi) ^ (r & 7)) << 4));
            }
            #pragma unroll
            for (int nj = 0; nj < 2; ++nj) {
                const int r = nW + 16 * nj + lrow;
                ldsm4(bfr[nj], bB + r * 128 + ((((ks << 1) | lhi) ^ (r & 7)) << 4));
            }
            #pragma unroll
            for (int mi = 0; mi < 4; ++mi)
                #pragma unroll
                for (int ni = 0; ni < 4; ++ni)
                    mma16816(acc[mi][ni], afr[mi],
                             bfr[ni >> 1][ni & 1], bfr[ni >> 1][(ni & 1) + 2]);
        }
        __syncthreads();
    }

    #pragma unroll
    for (int mi = 0; mi < 4; ++mi) {
        const int m = m0 + mW + 16 * mi + (lane >> 2);
        #pragma unroll
        for (int ni = 0; ni < 4; ++ni) {
            const int d = d0 + nW + 8 * ni + 2 * (lane & 3);
            *(float2*)&gOut[(size_t)m * CC + d] =
                make_float2(acc[mi][ni][0], acc[mi][ni][1]);
            *(float2*)&gOut[(size_t)(m + 8) * CC + d] =
                make_float2(acc[mi][ni][2], acc[mi][ni][3]);
        }
    }
}

// ---------------------------------------------------------------------------
// Kernel 4: row softmax over 256 cols, fp32 in -> bf16 out.
// ---------------------------------------------------------------------------
__global__ void __launch_bounds__(256) softmax_k() {
    const int idx = blockIdx.x;
    const bool first = idx < BB * CC;
    const size_t rb = (size_t)(idx & (BB * CC - 1)) * CC;
    const float* p = (first ? g_attn1 : g_attn2) + rb;
    __nv_bfloat16* q = (first ? g_ab1 : g_ab2) + rb;

    const int lane = threadIdx.x & 31, w = threadIdx.x >> 5;
    __shared__ float sh[8];
    __shared__ float s_bcast;

    float v = p[threadIdx.x];
    float m = v;
    #pragma unroll
    for (int o = 16; o; o >>= 1) m = fmaxf(m, __shfl_xor_sync(0xffffffffu, m, o));
    if (lane == 0) sh[w] = m;
    __syncthreads();
    if (threadIdx.x < 32) {
        float t = (lane < 8) ? sh[lane] : -INFINITY;
        #pragma unroll
        for (int o = 4; o; o >>= 1) t = fmaxf(t, __shfl_xor_sync(0xffffffffu, t, o));
        if (lane == 0) s_bcast = t;
    }
    __syncthreads();
    m = s_bcast;

    float e = expf(v - m);
    float s = e;
    #pragma unroll
    for (int o = 16; o; o >>= 1) s += __shfl_xor_sync(0xffffffffu, s, o);
    __syncthreads();
    if (lane == 0) sh[w] = s;
    __syncthreads();
    if (threadIdx.x < 32) {
        float t = (lane < 8) ? sh[lane] : 0.f;
        #pragma unroll
        for (int o = 4; o; o >>= 1) t += __shfl_xor_sync(0xffffffffu, t, o);
        if (lane == 0) s_bcast = t;
    }
    __syncthreads();

    q[threadIdx.x] = __float2bfloat16_rn(e * (1.f / s_bcast));
}

// ---------------------------------------------------------------------------
// Kernel 5: projection GEMM + residual, mma.sync bf16.
//   Per batch: D[4096, 256] = [x1t | x2t] (K=512) @ [ab1 | ab2]^T
//   out[b, n*256+c] = D[n,c] + x1[o] + x2[o]
//   CTA tile 128x128, BK=64 (8 chunks: 4 from part1, 4 from part2).
// ---------------------------------------------------------------------------
__global__ void __launch_bounds__(256) proj_mma(const float* __restrict__ x1,
                                                const float* __restrict__ x2,
                                                float* __restrict__ out) {
    extern __shared__ char smem[];
    const uint32_t sb = smem_to_u32(smem);
    const int tid = threadIdx.x, lane = tid & 31, wid = tid >> 5;
    const int b  = blockIdx.z;
    const int n0 = blockIdx.y * 128;              // spatial (M)
    const int c0 = blockIdx.x * 128;              // channel (N)

    const uint4* gA1 = (const uint4*)g_x1t + ((size_t)b * NN + n0) * (CC / 8);
    const uint4* gA2 = (const uint4*)g_x2t + ((size_t)b * NN + n0) * (CC / 8);
    const uint4* gB1 = (const uint4*)g_ab1 + ((size_t)(b * CC + c0)) * (CC / 8);
    const uint4* gB2 = (const uint4*)g_ab2 + ((size_t)(b * CC + c0)) * (CC / 8);

    const int mW = (wid >> 2) * 64;
    const int nW = (wid & 3) * 32;
    const int lrow = lane & 15;
    const int lhi  = lane >> 4;

    float acc[4][4][4] = {};

    auto prefetch = [&](int ch, int buf) {
        const uint4* pa = (ch < 4) ? gA1 : gA2;
        const uint4* pb = (ch < 4) ? gB1 : gB2;
        const int kc = (ch & 3) * 8;              // uint4 offset within 256-elem half
        const uint32_t aB = sb + buf * BUF_STRIDE;
        const uint32_t bB = aB + 16384;
        #pragma unroll
        for (int i = 0; i < 4; ++i) {
            const int lin = i * 256 + tid;
            const int r = lin >> 3, c = lin & 7;
            const uint32_t off = r * 128 + ((c ^ (r & 7)) << 4);
            cp16(aB + off, pa + (size_t)r * (CC / 8) + kc + c);
            cp16(bB + off, pb + (size_t)r * (CC / 8) + kc + c);
        }
        cp_commit();
    };

    prefetch(0, 0);
    for (int ch = 0; ch < 8; ++ch) {
        const int buf = ch & 1;
        if (ch + 1 < 8) { prefetch(ch + 1, buf ^ 1); cp_wait<1>(); }
        else            { cp_wait<0>(); }
        __syncthreads();

        const uint32_t aB = sb + buf * BUF_STRIDE;
        const uint32_t bB = aB + 16384;
        #pragma unroll
        for (int ks = 0; ks < 4; ++ks) {
            uint32_t afr[4][4], bfr[2][4];
            #pragma unroll
            for (int mi = 0; mi < 4; ++mi) {
                const int r = mW + 16 * mi + lrow;
                ldsm4(afr[mi], aB + r * 128 + ((((ks << 1) | lhi) ^ (r & 7)) << 4));
            }
            #pragma unroll
            for (int nj = 0; nj < 2; ++nj) {
                const int r = nW + 16 * nj + lrow;
                ldsm4(bfr[nj], bB + r * 128 + ((((ks << 1) | lhi) ^ (r & 7)) << 4));
            }
            #pragma unroll
            for (int mi = 0; mi < 4; ++mi)
                #pragma unroll
                for (int ni = 0; ni < 4; ++ni)
                    mma16816(acc[mi][ni], afr[mi],
                             bfr[ni >> 1][ni & 1], bfr[ni >> 1][(ni & 1) + 2]);
        }
        __syncthreads();
    }

    // Epilogue: out[o] = acc + x1[o] + x2[o],  o = b*CC*NN + n*CC + c
    const size_t ob = (size_t)b * CC * NN;
    #pragma unroll
    for (int mi = 0; mi < 4; ++mi) {
        const int n = n0 + mW + 16 * mi + (lane >> 2);
        #pragma unroll
        for (int ni = 0; ni < 4; ++ni) {
            const int c = c0 + nW + 8 * ni + 2 * (lane & 3);
            {
                const size_t o = ob + (size_t)n * CC + c;
                float2 r1 = *(const float2*)(x1 + o);
                float2 r2 = *(const float2*)(x2 + o);
                *(float2*)(out + o) = make_float2(acc[mi][ni][0] + r1.x + r2.x,
                                                  acc[mi][ni][1] + r1.y + r2.y);
            }
            {
                const size_t o = ob + (size_t)(n + 8) * CC + c;
                float2 r1 = *(const float2*)(x1 + o);
                float2 r2 = *(const float2*)(x2 + o);
                *(float2*)(out + o) = make_float2(acc[mi][ni][2] + r1.x + r2.x,
                                                  acc[mi][ni][3] + r1.y + r2.y);
            }
        }
    }
}

// ---------------------------------------------------------------------------
extern "C" void kernel_launch(void* const* d_in, const int* in_sizes, int n_in,
                              void* d_out, int out_size) {
    const float* x1 = (const float*)d_in[0];
    const float* x2 = (const float*)d_in[1];
    float* out = (float*)d_out;

    cudaFuncSetAttribute(score_mma, cudaFuncAttributeMaxDynamicSharedMemorySize, GEMM_SMEM);
    cudaFuncSetAttribute(proj_mma,  cudaFuncAttributeMaxDynamicSharedMemorySize, GEMM_SMEM);

    fuse_k     <<<BB * CC, 256>>>(x1, x2);
    transpose_k<<<dim3(NN / 32, CC / 32, BB), dim3(32, 8)>>>(x1, x2);
    score_mma  <<<dim3(4, 2, BB), 256, GEMM_SMEM>>>();
    softmax_k  <<<2 * BB * CC, 256>>>();
    proj_mma   <<<dim3(2, 32, BB), 256, GEMM_SMEM>>>(x1, x2, out);
}

// round 4
// speedup vs baseline: 4.9117x; 1.0518x over previous
#include <cuda_runtime.h>
#include <cuda_bf16.h>
#include <cstdint>
#include <math.h>

#define BB 16
#define CC 256
#define NN 4096

// ---------------------------------------------------------------------------
// Device-global scratch (allocation-free per harness rules)
// ---------------------------------------------------------------------------
static __device__ __nv_bfloat16 g_s  [(size_t)BB * CC * NN];  // s = x11 + x21
static __device__ __nv_bfloat16 g_x11[(size_t)BB * CC * NN];  // x1 row-normalized
static __device__ __nv_bfloat16 g_x21[(size_t)BB * CC * NN];  // x2 row-normalized
static __device__ __nv_bfloat16 g_x1t[(size_t)BB * CC * NN];  // x1 transposed [b,n,d]
static __device__ __nv_bfloat16 g_x2t[(size_t)BB * CC * NN];
static __device__ __nv_bfloat16 g_ab1[(size_t)BB * CC * CC];  // softmaxed, bf16
static __device__ __nv_bfloat16 g_ab2[(size_t)BB * CC * CC];

// ---------------------------------------------------------------------------
// PTX helpers (base PTX only: cp.async / ldmatrix / mma.sync — compute_103 safe)
// ---------------------------------------------------------------------------
__device__ __forceinline__ uint32_t smem_to_u32(const void* p) {
    uint32_t a;
    asm("{ .reg .u64 t; cvta.to.shared.u64 t, %1; cvt.u32.u64 %0, t; }"
        : "=r"(a) : "l"(p));
    return a;
}

__device__ __forceinline__ void cp16(uint32_t dst, const void* src) {
    asm volatile("cp.async.cg.shared.global [%0], [%1], 16;\n"
                 :: "r"(dst), "l"(src));
}
__device__ __forceinline__ void cp_commit() {
    asm volatile("cp.async.commit_group;" ::: "memory");
}
template <int N>
__device__ __forceinline__ void cp_wait() {
    asm volatile("cp.async.wait_group %0;" :: "n"(N) : "memory");
}

__device__ __forceinline__ void ldsm4(uint32_t* r, uint32_t addr) {
    asm volatile("ldmatrix.sync.aligned.m8n8.x4.shared.b16 {%0,%1,%2,%3}, [%4];"
                 : "=r"(r[0]), "=r"(r[1]), "=r"(r[2]), "=r"(r[3])
                 : "r"(addr));
}

__device__ __forceinline__ void mma16816(float* c, const uint32_t* a,
                                         uint32_t b0, uint32_t b1) {
    asm volatile(
        "mma.sync.aligned.m16n8k16.row.col.f32.bf16.bf16.f32 "
        "{%0,%1,%2,%3}, {%4,%5,%6,%7}, {%8,%9}, {%0,%1,%2,%3};"
        : "+f"(c[0]), "+f"(c[1]), "+f"(c[2]), "+f"(c[3])
        : "r"(a[0]), "r"(a[1]), "r"(a[2]), "r"(a[3]), "r"(b0), "r"(b1));
}

__device__ __forceinline__ uint32_t pack2bf(float x, float y) {
    __nv_bfloat162 h = __floats2bfloat162_rn(x, y);
    return *reinterpret_cast<uint32_t*>(&h);
}
__device__ __forceinline__ uint2 pack4bf(float a, float b, float c, float d) {
    return make_uint2(pack2bf(a, b), pack2bf(c, d));
}

// ---------------------------------------------------------------------------
// Kernel 1: fused norm + bf16 conversion.  One block per (b,c) row.
// ---------------------------------------------------------------------------
__global__ void __launch_bounds__(256) fuse_k(const float* __restrict__ x1,
                                              const float* __restrict__ x2) {
    const int row = blockIdx.x;
    const size_t base4 = (size_t)row * (NN / 4);
    const float4* p1 = ((const float4*)x1) + base4;
    const float4* p2 = ((const float4*)x2) + base4;

    float4 a[4], c[4];
    float s1 = 0.f, s2 = 0.f;
    #pragma unroll
    for (int i = 0; i < 4; ++i) {
        a[i] = p1[threadIdx.x + i * 256];
        c[i] = p2[threadIdx.x + i * 256];
        s1 += a[i].x * a[i].x + a[i].y * a[i].y + a[i].z * a[i].z + a[i].w * a[i].w;
        s2 += c[i].x * c[i].x + c[i].y * c[i].y + c[i].z * c[i].z + c[i].w * c[i].w;
    }
    __shared__ float sh1[8], sh2[8];
    __shared__ float b_i1, b_i2;
    const int lane = threadIdx.x & 31, w = threadIdx.x >> 5;
    #pragma unroll
    for (int o = 16; o; o >>= 1) {
        s1 += __shfl_xor_sync(0xffffffffu, s1, o);
        s2 += __shfl_xor_sync(0xffffffffu, s2, o);
    }
    if (lane == 0) { sh1[w] = s1; sh2[w] = s2; }
    __syncthreads();
    if (threadIdx.x < 32) {
        s1 = (lane < 8) ? sh1[lane] : 0.f;
        s2 = (lane < 8) ? sh2[lane] : 0.f;
        #pragma unroll
        for (int o = 4; o; o >>= 1) {
            s1 += __shfl_xor_sync(0xffffffffu, s1, o);
            s2 += __shfl_xor_sync(0xffffffffu, s2, o);
        }
        if (lane == 0) {
            b_i1 = 1.f / fmaxf(sqrtf(s1), 1e-12f);
            b_i2 = 1.f / fmaxf(sqrtf(s2), 1e-12f);
        }
    }
    __syncthreads();
    const float i1 = b_i1, i2 = b_i2;

    uint2* os  = reinterpret_cast<uint2*>(g_s)   + base4;
    uint2* o11 = reinterpret_cast<uint2*>(g_x11) + base4;
    uint2* o21 = reinterpret_cast<uint2*>(g_x21) + base4;
    #pragma unroll
    for (int i = 0; i < 4; ++i) {
        const int idx = threadIdx.x + i * 256;
        float n1x = a[i].x * i1, n1y = a[i].y * i1, n1z = a[i].z * i1, n1w = a[i].w * i1;
        float n2x = c[i].x * i2, n2y = c[i].y * i2, n2z = c[i].z * i2, n2w = c[i].w * i2;
        o11[idx] = pack4bf(n1x, n1y, n1z, n1w);
        o21[idx] = pack4bf(n2x, n2y, n2z, n2w);
        os [idx] = pack4bf(n1x + n2x, n1y + n2y, n1z + n2z, n1w + n2w);
    }
}

// ---------------------------------------------------------------------------
// Kernel 2: transpose x1, x2 -> bf16 [b, n, d]
// ---------------------------------------------------------------------------
__global__ void __launch_bounds__(256) transpose_k(const float* __restrict__ x1,
                                                   const float* __restrict__ x2) {
    __shared__ float t1[32][33], t2[32][33];
    const int b  = blockIdx.z;
    const int c0 = blockIdx.y * 32;
    const int n0 = blockIdx.x * 32;
    const int tx = threadIdx.x, ty = threadIdx.y;   // 32 x 8

    #pragma unroll
    for (int i = 0; i < 4; ++i) {
        const int r = ty + i * 8;
        const size_t idx = ((size_t)(b * CC + c0 + r)) * NN + n0 + tx;
        t1[r][tx] = x1[idx];
        t2[r][tx] = x2[idx];
    }
    __syncthreads();
    #pragma unroll
    for (int i = 0; i < 4; ++i) {
        const int r = ty + i * 8;
        const size_t o = ((size_t)b * NN + n0 + r) * CC + c0 + tx;
        g_x1t[o] = __float2bfloat16_rn(t1[tx][r]);
        g_x2t[o] = __float2bfloat16_rn(t2[tx][r]);
    }
}

// ---------------------------------------------------------------------------
// Kernel 3: score GEMM + fused softmax, mma.sync bf16.
//   Per CTA: scores[64, 256] = s[m0:m0+64, :4096] @ bsel[0:256, :4096]^T
//   then row-softmax in smem, write bf16 probabilities to g_ab{1,2}.
//   blockIdx.x: bit2 = sel (0 -> x11/ab1, 1 -> x21/ab2), bits 0:1 = m-tile.
//   8 warps as 2(m) x 4(d); warp tile 32x64; acc[2][8][4] = 64 fp32/thread.
//   smem: 2 x (A 8KB + B 32KB) double-buffered + 64x268 fp32 stash.
// ---------------------------------------------------------------------------
#define SC_BUF    40960                 // A (64x64x2=8192) + B (256x64x2=32768)
#define SC_STASH  (2 * SC_BUF)          // 81920
#define SC_SP     268                   // stash row stride (floats), de-banked
#define SC_SMEM   (SC_STASH + 64 * SC_SP * 4)   // 150528

__global__ void __launch_bounds__(256) score_mma() {
    extern __shared__ char smem[];
    const uint32_t sb = smem_to_u32(smem);
    const int tid = threadIdx.x, lane = tid & 31, wid = tid >> 5;
    const int b   = blockIdx.y;
    const int sel = blockIdx.x >> 2;
    const int m0  = (blockIdx.x & 3) * 64;

    const __nv_bfloat16* bsrc = sel ? g_x21 : g_x11;
    __nv_bfloat16* gOut = (sel ? g_ab2 : g_ab1) + (size_t)b * CC * CC;
    const uint4* gA = (const uint4*)g_s  + (size_t)(b * CC + m0) * (NN / 8);
    const uint4* gB = (const uint4*)bsrc + (size_t)(b * CC) * (NN / 8);

    const int mW = (wid >> 2) * 32;               // warp m offset (0/32)
    const int nW = (wid & 3) * 64;                // warp d offset (0..192)
    const int lrow = lane & 15;
    const int lhi  = lane >> 4;

    float acc[2][8][4] = {};

    auto prefetch = [&](int ch, int buf) {
        const uint32_t aB = sb + buf * SC_BUF;
        const uint32_t bB = aB + 8192;
        // A: 64 rows x 8 uint4 = 512 -> 2 per thread
        #pragma unroll
        for (int i = 0; i < 2; ++i) {
            const int lin = i * 256 + tid;
            const int r = lin >> 3, c = lin & 7;
            cp16(aB + r * 128 + ((c ^ (r & 7)) << 4),
                 gA + (size_t)r * (NN / 8) + ch * 8 + c);
        }
        // B: 256 rows x 8 uint4 = 2048 -> 8 per thread
        #pragma unroll
        for (int i = 0; i < 8; ++i) {
            const int lin = i * 256 + tid;
            const int r = lin >> 3, c = lin & 7;
            cp16(bB + r * 128 + ((c ^ (r & 7)) << 4),
                 gB + (size_t)r * (NN / 8) + ch * 8 + c);
        }
        cp_commit();
    };

    prefetch(0, 0);
    for (int ch = 0; ch < NN / 64; ++ch) {
        const int buf = ch & 1;
        if (ch + 1 < NN / 64) { prefetch(ch + 1, buf ^ 1); cp_wait<1>(); }
        else                  { cp_wait<0>(); }
        __syncthreads();

        const uint32_t aB = sb + buf * SC_BUF;
        const uint32_t bB = aB + 8192;
        #pragma unroll
        for (int ks = 0; ks < 4; ++ks) {
            uint32_t afr[2][4], bfr[4][4];
            #pragma unroll
            for (int mi = 0; mi < 2; ++mi) {
                const int r = mW + 16 * mi + lrow;
                ldsm4(afr[mi], aB + r * 128 + ((((ks << 1) | lhi) ^ (r & 7)) << 4));
            }
            #pragma unroll
            for (int nj = 0; nj < 4; ++nj) {
                const int r = nW + 16 * nj + lrow;
                ldsm4(bfr[nj], bB + r * 128 + ((((ks << 1) | lhi) ^ (r & 7)) << 4));
            }
            #pragma unroll
            for (int mi = 0; mi < 2; ++mi)
                #pragma unroll
                for (int ni = 0; ni < 8; ++ni)
                    mma16816(acc[mi][ni], afr[mi],
                             bfr[ni >> 1][ni & 1], bfr[ni >> 1][(ni & 1) + 2]);
        }
        __syncthreads();
    }

    // Stash scores to smem (padded stride), then per-warp row softmax.
    float* stash = (float*)(smem + SC_STASH);
    #pragma unroll
    for (int mi = 0; mi < 2; ++mi) {
        const int r = mW + 16 * mi + (lane >> 2);
        #pragma unroll
        for (int ni = 0; ni < 8; ++ni) {
            const int d = nW + 8 * ni + 2 * (lane & 3);
            *(float2*)&stash[(size_t)r * SC_SP + d] =
                make_float2(acc[mi][ni][0], acc[mi][ni][1]);
            *(float2*)&stash[(size_t)(r + 8) * SC_SP + d] =
                make_float2(acc[mi][ni][2], acc[mi][ni][3]);
        }
    }
    __syncthreads();

    // Each warp handles 8 rows; lane reads cols lane + 32*j (conflict-free).
    #pragma unroll
    for (int i = 0; i < 8; ++i) {
        const int r = wid * 8 + i;
        const float* srow = stash + (size_t)r * SC_SP;
        float v[8];
        #pragma unroll
        for (int j = 0; j < 8; ++j) v[j] = srow[lane + 32 * j];
        float m = v[0];
        #pragma unroll
        for (int j = 1; j < 8; ++j) m = fmaxf(m, v[j]);
        #pragma unroll
        for (int o = 16; o; o >>= 1) m = fmaxf(m, __shfl_xor_sync(0xffffffffu, m, o));
        float e[8], s = 0.f;
        #pragma unroll
        for (int j = 0; j < 8; ++j) { e[j] = __expf(v[j] - m); s += e[j]; }
        #pragma unroll
        for (int o = 16; o; o >>= 1) s += __shfl_xor_sync(0xffffffffu, s, o);
        const float inv = 1.f / s;
        __nv_bfloat16* q = gOut + (size_t)(m0 + r) * CC;
        #pragma unroll
        for (int j = 0; j < 8; ++j)
            q[lane + 32 * j] = __float2bfloat16_rn(e[j] * inv);
    }
}

// ---------------------------------------------------------------------------
// Kernel 5: projection GEMM + residual, mma.sync bf16.
//   Per batch: D[4096, 256] = [x1t | x2t] (K=512) @ [ab1 | ab2]^T
//   out[b, n*256+c] = D[n,c] + x1[o] + x2[o]
//   CTA tile 128x128, BK=64 (8 chunks: 4 from part1, 4 from part2).
// ---------------------------------------------------------------------------
#define PJ_BUF  32768
#define PJ_SMEM (2 * PJ_BUF)

__global__ void __launch_bounds__(256) proj_mma(const float* __restrict__ x1,
                                                const float* __restrict__ x2,
                                                float* __restrict__ out) {
    extern __shared__ char smem[];
    const uint32_t sb = smem_to_u32(smem);
    const int tid = threadIdx.x, lane = tid & 31, wid = tid >> 5;
    const int b  = blockIdx.z;
    const int n0 = blockIdx.y * 128;              // spatial (M)
    const int c0 = blockIdx.x * 128;              // channel (N)

    const uint4* gA1 = (const uint4*)g_x1t + ((size_t)b * NN + n0) * (CC / 8);
    const uint4* gA2 = (const uint4*)g_x2t + ((size_t)b * NN + n0) * (CC / 8);
    const uint4* gB1 = (const uint4*)g_ab1 + ((size_t)(b * CC + c0)) * (CC / 8);
    const uint4* gB2 = (const uint4*)g_ab2 + ((size_t)(b * CC + c0)) * (CC / 8);

    const int mW = (wid >> 2) * 64;
    const int nW = (wid & 3) * 32;
    const int lrow = lane & 15;
    const int lhi  = lane >> 4;

    float acc[4][4][4] = {};

    auto prefetch = [&](int ch, int buf) {
        const uint4* pa = (ch < 4) ? gA1 : gA2;
        const uint4* pb = (ch < 4) ? gB1 : gB2;
        const int kc = (ch & 3) * 8;              // uint4 offset within 256-elem half
        const uint32_t aB = sb + buf * PJ_BUF;
        const uint32_t bB = aB + 16384;
        #pragma unroll
        for (int i = 0; i < 4; ++i) {
            const int lin = i * 256 + tid;
            const int r = lin >> 3, c = lin & 7;
            const uint32_t off = r * 128 + ((c ^ (r & 7)) << 4);
            cp16(aB + off, pa + (size_t)r * (CC / 8) + kc + c);
            cp16(bB + off, pb + (size_t)r * (CC / 8) + kc + c);
        }
        cp_commit();
    };

    prefetch(0, 0);
    for (int ch = 0; ch < 8; ++ch) {
        const int buf = ch & 1;
        if (ch + 1 < 8) { prefetch(ch + 1, buf ^ 1); cp_wait<1>(); }
        else            { cp_wait<0>(); }
        __syncthreads();

        const uint32_t aB = sb + buf * PJ_BUF;
        const uint32_t bB = aB + 16384;
        #pragma unroll
        for (int ks = 0; ks < 4; ++ks) {
            uint32_t afr[4][4], bfr[2][4];
            #pragma unroll
            for (int mi = 0; mi < 4; ++mi) {
                const int r = mW + 16 * mi + lrow;
                ldsm4(afr[mi], aB + r * 128 + ((((ks << 1) | lhi) ^ (r & 7)) << 4));
            }
            #pragma unroll
            for (int nj = 0; nj < 2; ++nj) {
                const int r = nW + 16 * nj + lrow;
                ldsm4(bfr[nj], bB + r * 128 + ((((ks << 1) | lhi) ^ (r & 7)) << 4));
            }
            #pragma unroll
            for (int mi = 0; mi < 4; ++mi)
                #pragma unroll
                for (int ni = 0; ni < 4; ++ni)
                    mma16816(acc[mi][ni], afr[mi],
                             bfr[ni >> 1][ni & 1], bfr[ni >> 1][(ni & 1) + 2]);
        }
        __syncthreads();
    }

    // Epilogue: out[o] = acc + x1[o] + x2[o],  o = b*CC*NN + n*CC + c
    const size_t ob = (size_t)b * CC * NN;
    #pragma unroll
    for (int mi = 0; mi < 4; ++mi) {
        const int n = n0 + mW + 16 * mi + (lane >> 2);
        #pragma unroll
        for (int ni = 0; ni < 4; ++ni) {
            const int c = c0 + nW + 8 * ni + 2 * (lane & 3);
            {
                const size_t o = ob + (size_t)n * CC + c;
                float2 r1 = *(const float2*)(x1 + o);
                float2 r2 = *(const float2*)(x2 + o);
                *(float2*)(out + o) = make_float2(acc[mi][ni][0] + r1.x + r2.x,
                                                  acc[mi][ni][1] + r1.y + r2.y);
            }
            {
                const size_t o = ob + (size_t)(n + 8) * CC + c;
                float2 r1 = *(const float2*)(x1 + o);
                float2 r2 = *(const float2*)(x2 + o);
                *(float2*)(out + o) = make_float2(acc[mi][ni][2] + r1.x + r2.x,
                                                  acc[mi][ni][3] + r1.y + r2.y);
            }
        }
    }
}

// ---------------------------------------------------------------------------
extern "C" void kernel_launch(void* const* d_in, const int* in_sizes, int n_in,
                              void* d_out, int out_size) {
    const float* x1 = (const float*)d_in[0];
    const float* x2 = (const float*)d_in[1];
    float* out = (float*)d_out;

    cudaFuncSetAttribute(score_mma, cudaFuncAttributeMaxDynamicSharedMemorySize, SC_SMEM);
    cudaFuncSetAttribute(proj_mma,  cudaFuncAttributeMaxDynamicSharedMemorySize, PJ_SMEM);

    fuse_k     <<<BB * CC, 256>>>(x1, x2);
    transpose_k<<<dim3(NN / 32, CC / 32, BB), dim3(32, 8)>>>(x1, x2);
    score_mma  <<<dim3(8, BB), 256, SC_SMEM>>>();
    proj_mma   <<<dim3(2, 32, BB), 256, PJ_SMEM>>>(x1, x2, out);
}